// round 2
// baseline (speedup 1.0000x reference)
#include <cuda_runtime.h>
#include <cstdint>

#define NBLOCKS 2048
#define NTHREADS 256
#define EPS 1e-7

// Per-block partial sums (static scratch; no dynamic allocation allowed).
__device__ float g_tp0[NBLOCKS];
__device__ float g_tp1[NBLOCKS];
__device__ float g_cnt1[NBLOCKS];

// Pass 1: grid-stride over 4-element vectors.
// Per element with label t (int32, 0/1) and pred p:
//   c = min(p, 1-p)            (= yp[0])
//   t==0: tp0 += c             (label-0 "true positive" prob mass)
//   t==1: tp1 += 1-c, cnt1++   (label-1 mass + count)
// Every other confusion-matrix term derives from {tp0, tp1, cnt1, N}.
__global__ __launch_bounds__(NTHREADS) void f1_partial_kernel(
    const float4* __restrict__ pred4,
    const int4*  __restrict__ lab4,
    int nvec,              // number of float4/int4 vectors
    int n_total)           // total elements (scalar tail)
{
    float tp0 = 0.0f, tp1 = 0.0f;
    int cnt1 = 0;

    const int stride = gridDim.x * blockDim.x;
    for (int i = blockIdx.x * blockDim.x + threadIdx.x; i < nvec; i += stride) {
        float4 p = pred4[i];
        int4   t = lab4[i];

        float c0 = fminf(p.x, 1.0f - p.x);
        float c1 = fminf(p.y, 1.0f - p.y);
        float c2 = fminf(p.z, 1.0f - p.z);
        float c3 = fminf(p.w, 1.0f - p.w);

        // branchless: select accumulation target per label
        tp0 += (t.x == 0) ? c0 : 0.0f;
        tp0 += (t.y == 0) ? c1 : 0.0f;
        tp0 += (t.z == 0) ? c2 : 0.0f;
        tp0 += (t.w == 0) ? c3 : 0.0f;

        tp1 += (t.x != 0) ? (1.0f - c0) : 0.0f;
        tp1 += (t.y != 0) ? (1.0f - c1) : 0.0f;
        tp1 += (t.z != 0) ? (1.0f - c2) : 0.0f;
        tp1 += (t.w != 0) ? (1.0f - c3) : 0.0f;

        cnt1 += (t.x != 0) + (t.y != 0) + (t.z != 0) + (t.w != 0);
    }

    // Scalar tail (n_total % 4) — block 0 thread 0 only.
    if (blockIdx.x == 0 && threadIdx.x == 0) {
        const float* pred = (const float*)pred4;
        const int*   lab  = (const int*)lab4;
        for (int i = nvec * 4; i < n_total; i++) {
            float p = pred[i];
            float c = fminf(p, 1.0f - p);
            if (lab[i]) { tp1 += 1.0f - c; cnt1++; } else { tp0 += c; }
        }
    }

    // Warp reduce
    float fcnt = (float)cnt1;
    #pragma unroll
    for (int off = 16; off > 0; off >>= 1) {
        tp0  += __shfl_down_sync(0xFFFFFFFFu, tp0,  off);
        tp1  += __shfl_down_sync(0xFFFFFFFFu, tp1,  off);
        fcnt += __shfl_down_sync(0xFFFFFFFFu, fcnt, off);
    }

    __shared__ float s_tp0[NTHREADS / 32];
    __shared__ float s_tp1[NTHREADS / 32];
    __shared__ float s_c1 [NTHREADS / 32];
    int lane = threadIdx.x & 31;
    int wid  = threadIdx.x >> 5;
    if (lane == 0) { s_tp0[wid] = tp0; s_tp1[wid] = tp1; s_c1[wid] = fcnt; }
    __syncthreads();

    if (wid == 0) {
        tp0  = (lane < NTHREADS / 32) ? s_tp0[lane] : 0.0f;
        tp1  = (lane < NTHREADS / 32) ? s_tp1[lane] : 0.0f;
        fcnt = (lane < NTHREADS / 32) ? s_c1 [lane] : 0.0f;
        #pragma unroll
        for (int off = 16; off > 0; off >>= 1) {
            tp0  += __shfl_down_sync(0xFFFFFFFFu, tp0,  off);
            tp1  += __shfl_down_sync(0xFFFFFFFFu, tp1,  off);
            fcnt += __shfl_down_sync(0xFFFFFFFFu, fcnt, off);
        }
        if (lane == 0) {
            g_tp0[blockIdx.x]  = tp0;
            g_tp1[blockIdx.x]  = tp1;
            g_cnt1[blockIdx.x] = fcnt;
        }
    }
}

// Pass 2: one block reduces the NBLOCKS partials in double and computes the
// scalar loss per the reference formula.
__global__ __launch_bounds__(NTHREADS) void f1_final_kernel(
    float* __restrict__ out, long long n_total)
{
    double tp0 = 0.0, tp1 = 0.0, c1 = 0.0;
    for (int i = threadIdx.x; i < NBLOCKS; i += NTHREADS) {
        tp0 += (double)g_tp0[i];
        tp1 += (double)g_tp1[i];
        c1  += (double)g_cnt1[i];
    }

    __shared__ double s0[NTHREADS], s1[NTHREADS], s2[NTHREADS];
    s0[threadIdx.x] = tp0; s1[threadIdx.x] = tp1; s2[threadIdx.x] = c1;
    __syncthreads();
    for (int off = NTHREADS / 2; off > 0; off >>= 1) {
        if (threadIdx.x < off) {
            s0[threadIdx.x] += s0[threadIdx.x + off];
            s1[threadIdx.x] += s1[threadIdx.x + off];
            s2[threadIdx.x] += s2[threadIdx.x + off];
        }
        __syncthreads();
    }

    if (threadIdx.x == 0) {
        double TP0 = s0[0], TP1 = s1[0];
        double n1 = s2[0];
        double n0 = (double)n_total - n1;

        double fn0 = n0 - TP0;   // label-0 mass not captured by yp[0]
        double fn1 = n1 - TP1;
        double fp0 = fn1;        // yp[0] mass on label-1 rows
        double fp1 = fn0;

        double p0 = TP0 / (TP0 + fp0 + EPS);
        double r0 = TP0 / (TP0 + fn0 + EPS);
        double f1_0 = 2.0 * p0 * r0 / (p0 + r0 + EPS);

        double p1 = TP1 / (TP1 + fp1 + EPS);
        double r1 = TP1 / (TP1 + fn1 + EPS);
        double f1_1 = 2.0 * p1 * r1 / (p1 + r1 + EPS);

        f1_0 = fmin(fmax(f1_0, EPS), 1.0 - EPS);
        f1_1 = fmin(fmax(f1_1, EPS), 1.0 - EPS);

        out[0] = (float)(1.0 - 0.5 * (f1_0 + f1_1));
    }
}

extern "C" void kernel_launch(void* const* d_in, const int* in_sizes, int n_in,
                              void* d_out, int out_size)
{
    const float* y_pred = (const float*)d_in[0];
    const int*   y_true = (const int*)d_in[1];   // jnp.int64 w/o x64 -> int32
    int n = in_sizes[0];
    int nvec = n / 4;

    f1_partial_kernel<<<NBLOCKS, NTHREADS>>>(
        (const float4*)y_pred, (const int4*)y_true, nvec, n);
    f1_final_kernel<<<1, NTHREADS>>>((float*)d_out, (long long)n);
}